// round 2
// baseline (speedup 1.0000x reference)
#include <cuda_runtime.h>

#define RPB      128          // rows per block
#define NTHREADS 256          // 2 threads per row (unit halves)

// ---- shared memory layout (float offsets) ----
// Whh permuted per LSTM: [k(64)][half(2)][33 pad-slots of 8-unit groups... actually 33 unit slots][4 gates]
#define SZW      (64*2*33*4)            // 16896 floats per LSTM
#define OFF_W1   0
#define OFF_W2   (SZW)
#define OFF_H    (2*SZW)                // h staging: 128 rows x pitch 65
#define OFF_X    (OFF_H + RPB*65)       // inputs: 128 rows x pitch 19
#define OFF_WIH1 (OFF_X + RPB*19)
#define OFF_B1   (OFF_WIH1 + 256)
#define OFF_WIH2 (OFF_B1 + 256)
#define OFF_B2   (OFF_WIH2 + 256)
#define OFF_MW0  (OFF_B2 + 256)
#define OFF_MB0  (OFF_MW0 + 128)
#define OFF_MW1  (OFF_MB0 + 64)
#define OFF_MB1  (OFF_MW1 + 4096)
#define OFF_MW2  (OFF_MB1 + 64)
#define OFF_MB2  (OFF_MW2 + 2048)
#define OFF_PW   (OFF_MB2 + 32)
#define OFF_PB   (OFF_PW + 576)
#define SMEM_FLOATS (OFF_PB + 2)
#define SMEM_BYTES  (SMEM_FLOATS * 4)   // 210312 B < 227 KB cap

// ---- packed f32x2 helpers (Blackwell sm_103a) ----
__device__ __forceinline__ unsigned long long pack2(float a, float b) {
    unsigned long long r;
    asm("mov.b64 %0, {%1, %2};" : "=l"(r) : "f"(a), "f"(b));
    return r;
}
__device__ __forceinline__ void unpack2(unsigned long long v, float& a, float& b) {
    asm("mov.b64 {%0, %1}, %2;" : "=f"(a), "=f"(b) : "l"(v));
}
__device__ __forceinline__ void ffma2(unsigned long long& d, unsigned long long a, unsigned long long b) {
    asm("fma.rn.f32x2 %0, %1, %2, %0;" : "+l"(d) : "l"(a), "l"(b));
}

__device__ __forceinline__ float sigmoidf_(float x) {
    return __fdividef(1.0f, 1.0f + __expf(-x));
}
__device__ __forceinline__ float tanhf_(float x) {
    // values here are bounded (|x| < ~10); exp never overflows. ~1e-6 rel acc.
    float e = __expf(-2.0f * x);
    return __fdividef(1.0f - e, 1.0f + e);
}

__global__ void __launch_bounds__(NTHREADS, 1)
lstm_fused_kernel(const float* __restrict__ gin,
                  const float* __restrict__ Wih1, const float* __restrict__ Whh1,
                  const float* __restrict__ bih1, const float* __restrict__ bhh1,
                  const float* __restrict__ Wih2, const float* __restrict__ Whh2,
                  const float* __restrict__ bih2, const float* __restrict__ bhh2,
                  const float* __restrict__ mW0,  const float* __restrict__ mb0,
                  const float* __restrict__ mW1,  const float* __restrict__ mb1,
                  const float* __restrict__ mW2,  const float* __restrict__ mb2,
                  const float* __restrict__ pW,   const float* __restrict__ pb,
                  float* __restrict__ out)
{
    extern __shared__ float sm[];
    const int tid = threadIdx.x;

    // ---------------- staging ----------------
    {
        const float* src = gin + (size_t)blockIdx.x * RPB * 18;
        for (int i = tid; i < RPB * 18; i += NTHREADS)
            sm[OFF_X + (i / 18) * 19 + (i % 18)] = src[i];

        // Whh[gate_row(256)][k(64)]  ->  Wsh[k][half][unit0(0..31) pad 33][gate]
        for (int i = tid; i < 16384; i += NTHREADS) {
            int k = i & 63, rowi = i >> 6;        // rowi = g*64 + j
            int g = rowi >> 6, j = rowi & 63;
            int dst = ((k * 2 + (j >> 5)) * 33 + (j & 31)) * 4 + g;
            sm[OFF_W1 + dst] = Whh1[i];
            sm[OFF_W2 + dst] = Whh2[i];
        }
        for (int i = tid; i < 256; i += NTHREADS) {
            sm[OFF_WIH1 + i] = Wih1[i];  sm[OFF_B1 + i] = bih1[i] + bhh1[i];
            sm[OFF_WIH2 + i] = Wih2[i];  sm[OFF_B2 + i] = bih2[i] + bhh2[i];
        }
        for (int i = tid; i < 128;  i += NTHREADS) sm[OFF_MW0 + i] = mW0[i];
        for (int i = tid; i < 4096; i += NTHREADS) sm[OFF_MW1 + i] = mW1[i];
        for (int i = tid; i < 2048; i += NTHREADS) sm[OFF_MW2 + i] = mW2[i];
        for (int i = tid; i < 64;   i += NTHREADS) { sm[OFF_MB0 + i] = mb0[i]; sm[OFF_MB1 + i] = mb1[i]; }
        for (int i = tid; i < 576;  i += NTHREADS) sm[OFF_PW + i] = pW[i];
        if (tid < 32) sm[OFF_MB2 + tid] = mb2[tid];
        if (tid < 2)  sm[OFF_PB + tid]  = pb[tid];
        __syncthreads();
    }

    const int rl = tid >> 1;      // local row
    const int m  = tid & 1;       // unit half: owns units [m*32, m*32+32)
    float* hrow = sm + OFF_H + rl * 65;
    const float* xr = sm + OFF_X + rl * 19;

    float c[32], hn[32];
    float p0 = 0.f, p1 = 0.f;     // projection partials for both outputs

    #pragma unroll 1
    for (int l = 0; l < 2; ++l) {
        const float* W    = sm + (l ? OFF_W2   : OFF_W1);
        const float* wih  = sm + (l ? OFF_WIH2 : OFF_WIH1);
        const float* bsum = sm + (l ? OFF_B2   : OFF_B1);

        // ---- t = 0: h == 0, c == 0 -> gates = Wih*x + b ----
        {
            float x = xr[l * 8];
            #pragma unroll
            for (int u = 0; u < 32; ++u) {
                int j = m * 32 + u;
                float pi = fmaf(wih[j],       x, bsum[j]);
                float pg = fmaf(wih[128 + j], x, bsum[128 + j]);
                float po = fmaf(wih[192 + j], x, bsum[192 + j]);
                float iv = sigmoidf_(pi);
                float gv = tanhf_(pg);
                float ov = sigmoidf_(po);
                c[u]  = iv * gv;
                hn[u] = ov * tanhf_(c[u]);
            }
            __syncwarp();
            #pragma unroll
            for (int u = 0; u < 32; ++u) hrow[m * 32 + u] = hn[u];
            __syncwarp();
        }

        // ---- t = 1..7 ----
        #pragma unroll 1
        for (int t = 1; t < 8; ++t) {
            float x = xr[l * 8 + t];
            #pragma unroll
            for (int tile = 0; tile < 4; ++tile) {
                unsigned long long aIF[8], aGO[8];
                #pragma unroll
                for (int u = 0; u < 8; ++u) { aIF[u] = 0ull; aGO[u] = 0ull; }

                const float* wp = W + (m * 33 + tile * 8) * 4;
                #pragma unroll 4
                for (int k = 0; k < 64; ++k) {
                    float hk = hrow[k];
                    unsigned long long hk2 = pack2(hk, hk);
                    #pragma unroll
                    for (int u = 0; u < 8; ++u) {
                        ulonglong2 w = *reinterpret_cast<const ulonglong2*>(wp + u * 4);
                        ffma2(aIF[u], w.x, hk2);   // (i,f) gates
                        ffma2(aGO[u], w.y, hk2);   // (g,o) gates
                    }
                    wp += 264;                     // next k block (2*33*4 floats)
                }

                #pragma unroll
                for (int u = 0; u < 8; ++u) {
                    int ui = tile * 8 + u;
                    int j  = m * 32 + ui;
                    float aI, aF, aG, aO;
                    unpack2(aIF[u], aI, aF);
                    unpack2(aGO[u], aG, aO);
                    float pi = fmaf(wih[j],       x, aI + bsum[j]);
                    float pf = fmaf(wih[64 + j],  x, aF + bsum[64 + j]);
                    float pg = fmaf(wih[128 + j], x, aG + bsum[128 + j]);
                    float po = fmaf(wih[192 + j], x, aO + bsum[192 + j]);
                    float iv = sigmoidf_(pi), fv = sigmoidf_(pf);
                    float gv = tanhf_(pg),    ov = sigmoidf_(po);
                    c[ui]  = fmaf(fv, c[ui], iv * gv);
                    hn[ui] = ov * tanhf_(c[ui]);
                }
            }
            __syncwarp();
            #pragma unroll
            for (int u = 0; u < 32; ++u) hrow[m * 32 + u] = hn[u];
            __syncwarp();
        }

        // ---- projection partials for this LSTM: z-block [h(64), c(64)] ----
        {
            const float* pWs = sm + OFF_PW;
            int zb = l * 128 + m * 32;
            #pragma unroll
            for (int u = 0; u < 32; ++u) {
                p0 += hn[u] * pWs[zb + u]       + c[u] * pWs[zb + 64 + u];
                p1 += hn[u] * pWs[288 + zb + u] + c[u] * pWs[288 + zb + 64 + u];
            }
        }
    }

    // ---------------- MLP on feat ----------------
    {
        float f0 = xr[16], f1 = xr[17];
        #pragma unroll
        for (int u = 0; u < 32; ++u) {
            int j = m * 32 + u;
            float v = fmaf(sm[OFF_MW0 + j * 2], f0,
                      fmaf(sm[OFF_MW0 + j * 2 + 1], f1, sm[OFF_MB0 + j]));
            hn[u] = fmaxf(v, 0.f);
        }
        __syncwarp();
        #pragma unroll
        for (int u = 0; u < 32; ++u) hrow[m * 32 + u] = hn[u];
        __syncwarp();

        #pragma unroll
        for (int u = 0; u < 32; ++u) {
            int j = m * 32 + u;
            float acc = sm[OFF_MB1 + j];
            const float* wr = sm + OFF_MW1 + j * 64;
            #pragma unroll 8
            for (int k = 0; k < 64; ++k) acc = fmaf(hrow[k], wr[k], acc);
            hn[u] = fmaxf(acc, 0.f);
        }
        __syncwarp();
        #pragma unroll
        for (int u = 0; u < 32; ++u) hrow[m * 32 + u] = hn[u];
        __syncwarp();

        const float* pWs = sm + OFF_PW;
        #pragma unroll
        for (int u = 0; u < 16; ++u) {
            int j2 = m * 16 + u;
            float acc = sm[OFF_MB2 + j2];
            const float* wr = sm + OFF_MW2 + j2 * 64;
            #pragma unroll 8
            for (int k = 0; k < 64; ++k) acc = fmaf(hrow[k], wr[k], acc);
            p0 += acc * pWs[256 + j2];
            p1 += acc * pWs[288 + 256 + j2];
        }
    }

    // combine the two unit-halves of this row (adjacent lanes)
    p0 += __shfl_xor_sync(0xffffffffu, p0, 1);
    p1 += __shfl_xor_sync(0xffffffffu, p1, 1);

    size_t r = (size_t)blockIdx.x * RPB + (size_t)rl;
    out[r * 2 + m] = (m ? p1 : p0) + sm[OFF_PB + m];
}

extern "C" void kernel_launch(void* const* d_in, const int* in_sizes, int n_in,
                              void* d_out, int out_size)
{
    const float* gin  = (const float*)d_in[0];
    const float* Wih1 = (const float*)d_in[1];
    const float* Whh1 = (const float*)d_in[2];
    const float* bih1 = (const float*)d_in[3];
    const float* bhh1 = (const float*)d_in[4];
    const float* Wih2 = (const float*)d_in[5];
    const float* Whh2 = (const float*)d_in[6];
    const float* bih2 = (const float*)d_in[7];
    const float* bhh2 = (const float*)d_in[8];
    const float* mW0  = (const float*)d_in[9];
    const float* mb0  = (const float*)d_in[10];
    const float* mW1  = (const float*)d_in[11];
    const float* mb1  = (const float*)d_in[12];
    const float* mW2  = (const float*)d_in[13];
    const float* mb2  = (const float*)d_in[14];
    const float* pW   = (const float*)d_in[15];
    const float* pb   = (const float*)d_in[16];

    int rows = in_sizes[0] / 18;
    int grid = rows / RPB;

    cudaFuncSetAttribute(lstm_fused_kernel,
                         cudaFuncAttributeMaxDynamicSharedMemorySize, SMEM_BYTES);

    lstm_fused_kernel<<<grid, NTHREADS, SMEM_BYTES>>>(
        gin, Wih1, Whh1, bih1, bhh1, Wih2, Whh2, bih2, bhh2,
        mW0, mb0, mW1, mb1, mW2, mb2, pW, pb, (float*)d_out);
}

// round 3
// speedup vs baseline: 1.3505x; 1.3505x over previous
#include <cuda_runtime.h>

#define RPB      128
#define NTHREADS 256

// ---- shared memory layout (float offsets) ----
// Whh per LSTM: Wsh[k(64)][j(64)][4 gates (i,f,g,o)]  -> 16B per (k,j), broadcast-friendly
#define SZW      (64*64*4)              // 16384 floats
#define OFF_W1   0
#define OFF_W2   (SZW)
#define OFF_H    (2*SZW)                // h staging: 128 rows x pitch 68 (17 x 16B, conflict-free f4)
#define HPITCH   68
#define OFF_X    (OFF_H + RPB*HPITCH)   // inputs: 128 rows x pitch 19
#define OFF_WIH1 (OFF_X + RPB*19)
#define OFF_B1   (OFF_WIH1 + 256)
#define OFF_WIH2 (OFF_B1 + 256)
#define OFF_B2   (OFF_WIH2 + 256)
#define OFF_MW0  (OFF_B2 + 256)
#define OFF_MB0  (OFF_MW0 + 128)
#define OFF_MW1  (OFF_MB0 + 64)
#define OFF_MB1  (OFF_MW1 + 4096)
#define OFF_MW2  (OFF_MB1 + 64)
#define OFF_MB2  (OFF_MW2 + 2048)
#define OFF_PW   (OFF_MB2 + 32)
#define OFF_PB   (OFF_PW + 576)
#define OFF_PACC (OFF_PB + 2)           // per-row projection accumulators [128][2]
#define SMEM_FLOATS (OFF_PACC + RPB*2)
#define SMEM_BYTES  (SMEM_FLOATS * 4)   // ~208.8 KB < 227 KB

// ---- packed f32x2 helpers (Blackwell sm_103a) ----
__device__ __forceinline__ unsigned long long pack2(float a, float b) {
    unsigned long long r;
    asm("mov.b64 %0, {%1, %2};" : "=l"(r) : "f"(a), "f"(b));
    return r;
}
__device__ __forceinline__ void unpack2(unsigned long long v, float& a, float& b) {
    asm("mov.b64 {%0, %1}, %2;" : "=f"(a), "=f"(b) : "l"(v));
}
__device__ __forceinline__ void ffma2(unsigned long long& d, unsigned long long a, unsigned long long b) {
    asm("fma.rn.f32x2 %0, %1, %2, %0;" : "+l"(d) : "l"(a), "l"(b));
}

__device__ __forceinline__ float sigmoidf_(float x) {
    return __fdividef(1.0f, 1.0f + __expf(-x));
}
__device__ __forceinline__ float tanhf_(float x) {
    float e = __expf(-2.0f * x);
    return __fdividef(1.0f - e, 1.0f + e);
}

__global__ void __launch_bounds__(NTHREADS, 1)
lstm_fused_kernel(const float* __restrict__ gin,
                  const float* __restrict__ Wih1, const float* __restrict__ Whh1,
                  const float* __restrict__ bih1, const float* __restrict__ bhh1,
                  const float* __restrict__ Wih2, const float* __restrict__ Whh2,
                  const float* __restrict__ bih2, const float* __restrict__ bhh2,
                  const float* __restrict__ mW0,  const float* __restrict__ mb0,
                  const float* __restrict__ mW1,  const float* __restrict__ mb1,
                  const float* __restrict__ mW2,  const float* __restrict__ mb2,
                  const float* __restrict__ pW,   const float* __restrict__ pb,
                  float* __restrict__ out)
{
    extern __shared__ float sm[];
    const int tid = threadIdx.x;

    // ---------------- staging ----------------
    {
        const float* src = gin + (size_t)blockIdx.x * RPB * 18;
        for (int i = tid; i < RPB * 18; i += NTHREADS)
            sm[OFF_X + (i / 18) * 19 + (i % 18)] = src[i];

        // Whh[rowi = g*64 + j][k]  ->  Wsh[(k*64 + j)*4 + g]
        for (int i = tid; i < 16384; i += NTHREADS) {
            int k = i & 63, rowi = i >> 6;
            int g = rowi >> 6, j = rowi & 63;
            int dst = ((k << 6) + j) * 4 + g;
            sm[OFF_W1 + dst] = Whh1[i];
            sm[OFF_W2 + dst] = Whh2[i];
        }
        for (int i = tid; i < 256; i += NTHREADS) {
            sm[OFF_WIH1 + i] = Wih1[i];  sm[OFF_B1 + i] = bih1[i] + bhh1[i];
            sm[OFF_WIH2 + i] = Wih2[i];  sm[OFF_B2 + i] = bih2[i] + bhh2[i];
        }
        for (int i = tid; i < 128;  i += NTHREADS) sm[OFF_MW0 + i] = mW0[i];
        for (int i = tid; i < 4096; i += NTHREADS) sm[OFF_MW1 + i] = mW1[i];
        for (int i = tid; i < 2048; i += NTHREADS) sm[OFF_MW2 + i] = mW2[i];
        for (int i = tid; i < 64;   i += NTHREADS) { sm[OFF_MB0 + i] = mb0[i]; sm[OFF_MB1 + i] = mb1[i]; }
        for (int i = tid; i < 576;  i += NTHREADS) sm[OFF_PW + i] = pW[i];
        for (int i = tid; i < RPB * 2; i += NTHREADS) sm[OFF_PACC + i] = 0.f;
        if (tid < 32) sm[OFF_MB2 + tid] = mb2[tid];
        if (tid < 2)  sm[OFF_PB + tid]  = pb[tid];
        __syncthreads();
    }

    // warp w owns units [8w, 8w+8); lane l owns rows {l, l+32, l+64, l+96}
    const int wrp   = tid >> 5;
    const int lane  = tid & 31;
    const int jbase = wrp * 8;

    float c[4][8];
    float p0[4] = {0.f, 0.f, 0.f, 0.f};
    float p1[4] = {0.f, 0.f, 0.f, 0.f};

    #pragma unroll 1
    for (int lay = 0; lay < 2; ++lay) {
        const float* W    = sm + (lay ? OFF_W2   : OFF_W1);
        const float* wih  = sm + (lay ? OFF_WIH2 : OFF_WIH1);
        const float* bsum = sm + (lay ? OFF_B2   : OFF_B1);
        const ulonglong2* wp = reinterpret_cast<const ulonglong2*>(W) + jbase;

        // ---- t = 0 (h == 0, c == 0) ----
        {
            float x[4];
            #pragma unroll
            for (int i = 0; i < 4; ++i)
                x[i] = sm[OFF_X + (lane + 32 * i) * 19 + lay * 8];
            #pragma unroll
            for (int u = 0; u < 8; ++u) {
                int j = jbase + u;
                float wi = wih[j], wg = wih[128 + j], wo = wih[192 + j];
                float bi = bsum[j], bg = bsum[128 + j], bo = bsum[192 + j];
                #pragma unroll
                for (int i = 0; i < 4; ++i) {
                    float iv = sigmoidf_(fmaf(wi, x[i], bi));
                    float gv = tanhf_(fmaf(wg, x[i], bg));
                    float ov = sigmoidf_(fmaf(wo, x[i], bo));
                    c[i][u] = iv * gv;
                    sm[OFF_H + (lane + 32 * i) * HPITCH + j] = ov * tanhf_(c[i][u]);
                }
            }
            __syncthreads();
        }

        // ---- t = 1..7 ----
        #pragma unroll 1
        for (int t = 1; t < 8; ++t) {
            float x[4];
            #pragma unroll
            for (int i = 0; i < 4; ++i)
                x[i] = sm[OFF_X + (lane + 32 * i) * 19 + lay * 8 + t];

            unsigned long long aIF[4][8], aGO[4][8];
            #pragma unroll
            for (int i = 0; i < 4; ++i)
                #pragma unroll
                for (int u = 0; u < 8; ++u) { aIF[i][u] = 0ull; aGO[i][u] = 0ull; }

            const float4* h4p0 = reinterpret_cast<const float4*>(sm + OFF_H + (lane)      * HPITCH);
            const float4* h4p1 = reinterpret_cast<const float4*>(sm + OFF_H + (lane + 32) * HPITCH);
            const float4* h4p2 = reinterpret_cast<const float4*>(sm + OFF_H + (lane + 64) * HPITCH);
            const float4* h4p3 = reinterpret_cast<const float4*>(sm + OFF_H + (lane + 96) * HPITCH);

            #pragma unroll 2
            for (int kg = 0; kg < 16; ++kg) {
                float4 h4[4];
                h4[0] = h4p0[kg]; h4[1] = h4p1[kg]; h4[2] = h4p2[kg]; h4[3] = h4p3[kg];
                const float* hf = reinterpret_cast<const float*>(h4);
                #pragma unroll
                for (int kk = 0; kk < 4; ++kk) {
                    int k = kg * 4 + kk;
                    unsigned long long hk2[4];
                    #pragma unroll
                    for (int i = 0; i < 4; ++i) {
                        float hv = hf[i * 4 + kk];
                        hk2[i] = pack2(hv, hv);
                    }
                    const ulonglong2* wk = wp + (k << 6);
                    #pragma unroll
                    for (int u = 0; u < 8; ++u) {
                        ulonglong2 wv = wk[u];                  // broadcast across warp
                        ffma2(aIF[0][u], wv.x, hk2[0]); ffma2(aGO[0][u], wv.y, hk2[0]);
                        ffma2(aIF[1][u], wv.x, hk2[1]); ffma2(aGO[1][u], wv.y, hk2[1]);
                        ffma2(aIF[2][u], wv.x, hk2[2]); ffma2(aGO[2][u], wv.y, hk2[2]);
                        ffma2(aIF[3][u], wv.x, hk2[3]); ffma2(aGO[3][u], wv.y, hk2[3]);
                    }
                }
            }

            // epilogue: activations + state update
            #pragma unroll
            for (int u = 0; u < 8; ++u) {
                int j = jbase + u;
                float wi = wih[j],      wf = wih[64 + j];
                float wg = wih[128 + j], wo = wih[192 + j];
                float bi = bsum[j],      bf = bsum[64 + j];
                float bg = bsum[128 + j], bo = bsum[192 + j];
                #pragma unroll
                for (int i = 0; i < 4; ++i) {
                    float aI, aF, aG, aO;
                    unpack2(aIF[i][u], aI, aF);
                    unpack2(aGO[i][u], aG, aO);
                    float iv = sigmoidf_(aI + fmaf(wi, x[i], bi));
                    float fv = sigmoidf_(aF + fmaf(wf, x[i], bf));
                    float gv = tanhf_(   aG + fmaf(wg, x[i], bg));
                    float ov = sigmoidf_(aO + fmaf(wo, x[i], bo));
                    c[i][u] = fmaf(fv, c[i][u], iv * gv);
                    sm[OFF_H + (lane + 32 * i) * HPITCH + j] = ov * tanhf_(c[i][u]);
                }
            }
            __syncthreads();
        }

        // ---- projection partials for this LSTM: z = [h(64), c(64)] block ----
        {
            const float* pWs = sm + OFF_PW;
            int zb = lay * 128;
            #pragma unroll
            for (int u = 0; u < 8; ++u) {
                int j = jbase + u;
                float w0h = pWs[zb + j],       w0c = pWs[zb + 64 + j];
                float w1h = pWs[288 + zb + j], w1c = pWs[288 + zb + 64 + j];
                #pragma unroll
                for (int i = 0; i < 4; ++i) {
                    float h = sm[OFF_H + (lane + 32 * i) * HPITCH + j];  // own write
                    p0[i] = fmaf(h, w0h, fmaf(c[i][u], w0c, p0[i]));
                    p1[i] = fmaf(h, w1h, fmaf(c[i][u], w1c, p1[i]));
                }
            }
        }
    }

    // accumulate LSTM projection partials per row
    #pragma unroll
    for (int i = 0; i < 4; ++i) {
        atomicAdd(&sm[OFF_PACC + (lane + 32 * i) * 2 + 0], p0[i]);
        atomicAdd(&sm[OFF_PACC + (lane + 32 * i) * 2 + 1], p1[i]);
    }
    __syncthreads();

    // ---------------- MLP on feat (2 threads per row) ----------------
    {
        const int rl = tid >> 1;
        const int m  = tid & 1;
        float* hrow = sm + OFF_H + rl * HPITCH;
        const float* xr = sm + OFF_X + rl * 19;
        float f0 = xr[16], f1 = xr[17];

        #pragma unroll
        for (int u = 0; u < 32; ++u) {
            int j = m * 32 + u;
            float v = fmaf(sm[OFF_MW0 + j * 2], f0,
                      fmaf(sm[OFF_MW0 + j * 2 + 1], f1, sm[OFF_MB0 + j]));
            hrow[j] = fmaxf(v, 0.f);
        }
        __syncwarp();

        float r1[32];
        #pragma unroll
        for (int u = 0; u < 32; ++u) {
            int j = m * 32 + u;
            float acc = sm[OFF_MB1 + j];
            const float* wr = sm + OFF_MW1 + j * 64;
            #pragma unroll 8
            for (int k = 0; k < 64; ++k) acc = fmaf(hrow[k], wr[k], acc);
            r1[u] = fmaxf(acc, 0.f);
        }
        __syncwarp();
        #pragma unroll
        for (int u = 0; u < 32; ++u) hrow[m * 32 + u] = r1[u];
        __syncwarp();

        const float* pWs = sm + OFF_PW;
        float pa0 = 0.f, pa1 = 0.f;
        #pragma unroll
        for (int u2 = 0; u2 < 16; ++u2) {
            int j2 = m * 16 + u2;
            float acc = sm[OFF_MB2 + j2];
            const float* wr = sm + OFF_MW2 + j2 * 64;
            #pragma unroll 8
            for (int k = 0; k < 64; ++k) acc = fmaf(hrow[k], wr[k], acc);
            pa0 = fmaf(acc, pWs[256 + j2], pa0);
            pa1 = fmaf(acc, pWs[288 + 256 + j2], pa1);
        }
        atomicAdd(&sm[OFF_PACC + rl * 2 + 0], pa0);
        atomicAdd(&sm[OFF_PACC + rl * 2 + 1], pa1);
        __syncthreads();

        size_t r = (size_t)blockIdx.x * RPB + (size_t)rl;
        out[r * 2 + m] = sm[OFF_PACC + rl * 2 + m] + sm[OFF_PB + m];
    }
}

extern "C" void kernel_launch(void* const* d_in, const int* in_sizes, int n_in,
                              void* d_out, int out_size)
{
    const float* gin  = (const float*)d_in[0];
    const float* Wih1 = (const float*)d_in[1];
    const float* Whh1 = (const float*)d_in[2];
    const float* bih1 = (const float*)d_in[3];
    const float* bhh1 = (const float*)d_in[4];
    const float* Wih2 = (const float*)d_in[5];
    const float* Whh2 = (const float*)d_in[6];
    const float* bih2 = (const float*)d_in[7];
    const float* bhh2 = (const float*)d_in[8];
    const float* mW0  = (const float*)d_in[9];
    const float* mb0  = (const float*)d_in[10];
    const float* mW1  = (const float*)d_in[11];
    const float* mb1  = (const float*)d_in[12];
    const float* mW2  = (const float*)d_in[13];
    const float* mb2  = (const float*)d_in[14];
    const float* pW   = (const float*)d_in[15];
    const float* pb   = (const float*)d_in[16];

    int rows = in_sizes[0] / 18;
    int grid = rows / RPB;

    cudaFuncSetAttribute(lstm_fused_kernel,
                         cudaFuncAttributeMaxDynamicSharedMemorySize, SMEM_BYTES);

    lstm_fused_kernel<<<grid, NTHREADS, SMEM_BYTES>>>(
        gin, Wih1, Whh1, bih1, bhh1, Wih2, Whh2, bih2, bhh2,
        mW0, mb0, mW1, mb1, mW2, mb2, pW, pb, (float*)d_out);
}